// round 2
// baseline (speedup 1.0000x reference)
#include <cuda_runtime.h>
#include <cstdint>
#include <math.h>

#define NB 8
#define CIN 512
#define COUT 512
#define HH 50
#define WW 76
#define HW 3800
#define NANCH 34200
#define KTOT 4608
#define PRE 6000
#define POST 300
#define SORTN 65536
#define NW 94

#define OUT_LOCS 0
#define OUT_SCORES 1094400
#define OUT_ROIS 1641600
#define OUT_ANCH 1651200

// ---------------- static scratch ----------------
__device__ float g_wT[KTOT * COUT];                      // [k][m]
__device__ float g_feat[(size_t)NB * COUT * HW];         // [n][m][p]
__device__ float g_fg[NB * NANCH];
__device__ float g_boxes[(size_t)NB * NANCH * 4];
__device__ unsigned long long g_keys[(size_t)NB * SORTN];
__device__ float g_nbox[NB * PRE * 5];
__device__ unsigned char g_nfin[NB * PRE];
__device__ unsigned long long g_mask[(size_t)NB * PRE * NW];

// ---------------- helpers ----------------
__device__ __forceinline__ unsigned fenc(float f) {
    unsigned u = __float_as_uint(f);
    return (u & 0x80000000u) ? ~u : (u | 0x80000000u);
}
__device__ __forceinline__ float fdec(unsigned e) {
    return (e & 0x80000000u) ? __uint_as_float(e & 0x7FFFFFFFu)
                             : __uint_as_float(~e);
}
__device__ __forceinline__ float dimval(const void* p) {
    int v = *(const int*)p;
    if (v > 0 && v < 100000) return (float)v;
    return *(const float*)p;
}

// ---------------- weight transpose: w[m][c][ky][kx] -> g_wT[(s*512+c)][m] ----------------
__global__ void k_wT(const float* __restrict__ w) {
    int idx = blockIdx.x * 256 + threadIdx.x;
    if (idx >= KTOT * COUT) return;
    int k = idx >> 9;          // 0..4607
    int m = idx & 511;
    int s = k >> 9;            // 0..8
    int c = k & 511;
    int ky = s / 3, kx = s % 3;
    g_wT[(size_t)k * COUT + m] = w[(((size_t)m * CIN + c) * 3 + ky) * 3 + kx];
}

// ---------------- anchors -> out[OUT_ANCH] ----------------
__global__ void k_anchor(float* __restrict__ out) {
    int i = blockIdx.x * 256 + threadIdx.x;
    if (i >= NANCH) return;
    int a = i % 9, p = i / 9;
    int y = p / WW, x = p % WW;
    int ri = a / 3, si = a % 3;
    const float rat[3] = {0.5f, 1.0f, 2.0f};
    const float scl[3] = {8.0f, 16.0f, 32.0f};
    float h = 16.0f * scl[si] * sqrtf(rat[ri]);
    float w = 16.0f * scl[si] * sqrtf(1.0f / rat[ri]);
    // match reference rounding: base = (8 - w/2) first, then + shift
    float bx0 = 8.0f - w * 0.5f, by0 = 8.0f - h * 0.5f;
    float bx1 = 8.0f + w * 0.5f, by1 = 8.0f + h * 0.5f;
    float sx = x * 16.0f, sy = y * 16.0f;
    float* o = out + OUT_ANCH + (size_t)i * 4;
    o[0] = sx + bx0; o[1] = sy + by0; o[2] = sx + bx1; o[3] = sy + by1;
}

// ---------------- conv 3x3 + bias + relu as implicit GEMM ----------------
// M=512(cout), N=3800(pos), K=4608 (k = s*512+c). Tiles 128x128x8, 256 thr, 8x8 micro.
#define BK 8
__global__ __launch_bounds__(256, 2) void k_conv(const float* __restrict__ xin,
                                                 const float* __restrict__ bias) {
    int nb = blockIdx.z;
    int mtile = blockIdx.y * 128;
    int ntile = blockIdx.x * 128;
    int tid = threadIdx.x;
    int tx = tid & 15, ty = tid >> 4;

    __shared__ float As[2][BK][128];
    __shared__ float Bs[2][BK][128];

    int nn = tid & 127;
    int r0 = tid >> 7;  // 0/1
    int p = ntile + nn;
    int py = p / WW, px = p % WW;
    bool pvalid = (p < HW);
    int off[9];
    unsigned okm = 0;
#pragma unroll
    for (int s = 0; s < 9; ++s) {
        int dy = s / 3 - 1, dx = s % 3 - 1;
        int y2 = py + dy, x2 = px + dx;
        bool ok = pvalid && y2 >= 0 && y2 < HH && x2 >= 0 && x2 < WW;
        off[s] = y2 * WW + x2;
        if (ok) okm |= (1u << s);
    }
    const float* xb = xin + (size_t)nb * CIN * HW;

    float acc[8][8];
#pragma unroll
    for (int i = 0; i < 8; ++i)
#pragma unroll
        for (int j = 0; j < 8; ++j) acc[i][j] = 0.0f;

    float ar[4], br[4];
#pragma unroll
    for (int q = 0; q < 4; ++q) {
        int r = r0 + q * 2;
        int k = r;
        ar[q] = g_wT[(size_t)k * COUT + mtile + nn];
        int s = k >> 9, c = k & 511;
        br[q] = ((okm >> s) & 1) ? xb[(size_t)c * HW + off[s]] : 0.0f;
    }
#pragma unroll
    for (int q = 0; q < 4; ++q) {
        int r = r0 + q * 2;
        As[0][r][nn] = ar[q];
        Bs[0][r][nn] = br[q];
    }
    __syncthreads();

    int buf = 0;
    const int NT = KTOT / BK;  // 576
    for (int t = 0; t < NT; ++t) {
        if (t + 1 < NT) {
            int kt = (t + 1) * BK;
#pragma unroll
            for (int q = 0; q < 4; ++q) {
                int r = r0 + q * 2;
                int k = kt + r;
                ar[q] = g_wT[(size_t)k * COUT + mtile + nn];
                int s = k >> 9, c = k & 511;
                br[q] = ((okm >> s) & 1) ? xb[(size_t)c * HW + off[s]] : 0.0f;
            }
        }
#pragma unroll
        for (int kk = 0; kk < BK; ++kk) {
            float a[8], b[8];
#pragma unroll
            for (int i = 0; i < 8; ++i) a[i] = As[buf][kk][ty * 8 + i];
#pragma unroll
            for (int j = 0; j < 8; ++j) b[j] = Bs[buf][kk][tx * 8 + j];
#pragma unroll
            for (int i = 0; i < 8; ++i)
#pragma unroll
                for (int j = 0; j < 8; ++j) acc[i][j] += a[i] * b[j];
        }
        if (t + 1 < NT) {
#pragma unroll
            for (int q = 0; q < 4; ++q) {
                int r = r0 + q * 2;
                As[buf ^ 1][r][nn] = ar[q];
                Bs[buf ^ 1][r][nn] = br[q];
            }
            __syncthreads();
            buf ^= 1;
        }
    }
    // epilogue: bias + relu, store to g_feat[n][m][p]
#pragma unroll
    for (int i = 0; i < 8; ++i) {
        int m = mtile + ty * 8 + i;
        float bv = bias[m];
        float* dst = g_feat + (size_t)nb * COUT * HW + (size_t)m * HW;
#pragma unroll
        for (int j4 = 0; j4 < 2; ++j4) {
            int pp = ntile + tx * 8 + j4 * 4;
            if (pp < HW) {
                float4 v;
                v.x = fmaxf(acc[i][j4 * 4 + 0] + bv, 0.0f);
                v.y = fmaxf(acc[i][j4 * 4 + 1] + bv, 0.0f);
                v.z = fmaxf(acc[i][j4 * 4 + 2] + bv, 0.0f);
                v.w = fmaxf(acc[i][j4 * 4 + 3] + bv, 0.0f);
                *(float4*)(dst + pp) = v;
            }
        }
    }
}

// ---------------- heads: 1x1 convs (18 score + 36 loc) + softmax ----------------
__global__ __launch_bounds__(128) void k_heads(const float* __restrict__ swg,
                                               const float* __restrict__ sb,
                                               const float* __restrict__ lwg,
                                               const float* __restrict__ lb,
                                               float* __restrict__ out) {
    int nb = blockIdx.y;
    int p = blockIdx.x * 128 + threadIdx.x;
    __shared__ float sw[128 * 54];
    float acc[54];
#pragma unroll
    for (int o = 0; o < 54; ++o) acc[o] = 0.0f;
    const float* feat = g_feat + (size_t)nb * COUT * HW;

    for (int c0 = 0; c0 < CIN; c0 += 128) {
        for (int t = threadIdx.x; t < 128 * 54; t += 128) {
            int cl = t / 54, o = t % 54;
            sw[t] = (o < 18) ? swg[o * CIN + c0 + cl] : lwg[(o - 18) * CIN + c0 + cl];
        }
        __syncthreads();
        if (p < HW) {
            for (int cl = 0; cl < 128; ++cl) {
                float f = feat[(size_t)(c0 + cl) * HW + p];
                const float* wrow = &sw[cl * 54];
#pragma unroll
                for (int o = 0; o < 54; ++o) acc[o] += wrow[o] * f;
            }
        }
        __syncthreads();
    }
    if (p >= HW) return;
#pragma unroll
    for (int a = 0; a < 9; ++a) {
        float s0 = acc[a * 2 + 0] + sb[a * 2 + 0];
        float s1 = acc[a * 2 + 1] + sb[a * 2 + 1];
        float m = fmaxf(s0, s1);
        float e0 = expf(s0 - m), e1 = expf(s1 - m);
        float fg = e1 / (e0 + e1);
        size_t ai = (size_t)nb * NANCH + (size_t)p * 9 + a;
        out[OUT_SCORES + ai * 2 + 0] = s0;
        out[OUT_SCORES + ai * 2 + 1] = s1;
        g_fg[ai] = fg;
        float l0 = acc[18 + a * 4 + 0] + lb[a * 4 + 0];
        float l1 = acc[18 + a * 4 + 1] + lb[a * 4 + 1];
        float l2 = acc[18 + a * 4 + 2] + lb[a * 4 + 2];
        float l3 = acc[18 + a * 4 + 3] + lb[a * 4 + 3];
        out[OUT_LOCS + ai * 4 + 0] = l0;
        out[OUT_LOCS + ai * 4 + 1] = l1;
        out[OUT_LOCS + ai * 4 + 2] = l2;
        out[OUT_LOCS + ai * 4 + 3] = l3;
    }
}

// ---------------- decode boxes, clip, min-size filter, build sort keys ----------------
__global__ void k_decode(const float* __restrict__ out_ro,
                         const void* __restrict__ ph, const void* __restrict__ pw) {
    int nb = blockIdx.y;
    int i = blockIdx.x * 256 + threadIdx.x;
    if (i >= SORTN) return;
    unsigned long long key;
    if (i < NANCH) {
        float imH = dimval(ph), imW = dimval(pw);
        const float* an = out_ro + OUT_ANCH + (size_t)i * 4;
        size_t ai = (size_t)nb * NANCH + i;
        const float* lc = out_ro + OUT_LOCS + ai * 4;
        float ax0 = an[0], ay0 = an[1], ax1 = an[2], ay1 = an[3];
        float aw = ax1 - ax0, ah = ay1 - ay0;
        float actx = ax0 + 0.5f * aw, acty = ay0 + 0.5f * ah;
        float cx = lc[0] * aw + actx, cy = lc[1] * ah + acty;
        float w = expf(lc[2]) * aw, h = expf(lc[3]) * ah;
        float b0 = cx - 0.5f * w, b1 = cy - 0.5f * h;
        float b2 = cx + 0.5f * w, b3 = cy + 0.5f * h;
        b0 = fminf(fmaxf(b0, 0.0f), imW);
        b2 = fminf(fmaxf(b2, 0.0f), imW);
        b1 = fminf(fmaxf(b1, 0.0f), imH);
        b3 = fminf(fmaxf(b3, 0.0f), imH);
        bool valid = ((b2 - b0) >= 16.0f) && ((b3 - b1) >= 16.0f);
        float sc = valid ? g_fg[ai] : -INFINITY;
        float* bx = g_boxes + ai * 4;
        bx[0] = b0; bx[1] = b1; bx[2] = b2; bx[3] = b3;
        key = ((unsigned long long)(~fenc(sc)) << 32) | (unsigned)i;
    } else {
        key = ~0ULL;  // padding sorts last (ascending)
    }
    g_keys[(size_t)nb * SORTN + i] = key;
}

// ---------------- bitonic sort (ascending keys = descending scores) ----------------
__global__ __launch_bounds__(512) void k_sort_local() {
    __shared__ unsigned long long sk[4096];
    int nb = blockIdx.y;
    int base = blockIdx.x * 4096;
    unsigned long long* gk = g_keys + (size_t)nb * SORTN;
    for (int t = threadIdx.x; t < 4096; t += 512) sk[t] = gk[base + t];
    __syncthreads();
    for (int k = 2; k <= 4096; k <<= 1) {
        for (int j = k >> 1; j > 0; j >>= 1) {
#pragma unroll 4
            for (int q = 0; q < 4; ++q) {
                int l = q * 512 + threadIdx.x;
                int i = ((l & ~(j - 1)) << 1) | (l & (j - 1));
                bool asc = (((base + i) & k) == 0);
                unsigned long long a = sk[i], b = sk[i + j];
                bool swp = asc ? (a > b) : (a < b);
                if (swp) { sk[i] = b; sk[i + j] = a; }
            }
            __syncthreads();
        }
    }
    for (int t = threadIdx.x; t < 4096; t += 512) gk[base + t] = sk[t];
}

__global__ void k_sort_global(int k, int j) {
    int nb = blockIdx.y;
    int l = blockIdx.x * 256 + threadIdx.x;  // 0..32767
    unsigned long long* gk = g_keys + (size_t)nb * SORTN;
    int i = ((l & ~(j - 1)) << 1) | (l & (j - 1));
    bool asc = ((i & k) == 0);
    unsigned long long a = gk[i], b = gk[i + j];
    bool swp = asc ? (a > b) : (a < b);
    if (swp) { gk[i] = b; gk[i + j] = a; }
}

__global__ __launch_bounds__(512) void k_sort_tail(int k) {
    __shared__ unsigned long long sk[4096];
    int nb = blockIdx.y;
    int base = blockIdx.x * 4096;
    unsigned long long* gk = g_keys + (size_t)nb * SORTN;
    for (int t = threadIdx.x; t < 4096; t += 512) sk[t] = gk[base + t];
    __syncthreads();
    for (int j = 2048; j > 0; j >>= 1) {
#pragma unroll 4
        for (int q = 0; q < 4; ++q) {
            int l = q * 512 + threadIdx.x;
            int i = ((l & ~(j - 1)) << 1) | (l & (j - 1));
            bool asc = (((base + i) & k) == 0);
            unsigned long long a = sk[i], b = sk[i + j];
            bool swp = asc ? (a > b) : (a < b);
            if (swp) { sk[i] = b; sk[i + j] = a; }
        }
        __syncthreads();
    }
    for (int t = threadIdx.x; t < 4096; t += 512) gk[base + t] = sk[t];
}

// ---------------- gather top-6000 ----------------
__global__ void k_gather() {
    int nb = blockIdx.y;
    int r = blockIdx.x * 256 + threadIdx.x;
    if (r >= PRE) return;
    unsigned long long key = g_keys[(size_t)nb * SORTN + r];
    unsigned idx = (unsigned)(key & 0xFFFFFFFFu);
    unsigned hi = (unsigned)(key >> 32);
    float sc = fdec(~hi);
    const float* bx = g_boxes + ((size_t)nb * NANCH + idx) * 4;
    float b0 = bx[0], b1 = bx[1], b2 = bx[2], b3 = bx[3];
    float* dst = g_nbox + ((size_t)nb * PRE + r) * 5;
    dst[0] = b0; dst[1] = b1; dst[2] = b2; dst[3] = b3;
    dst[4] = (b2 - b0) * (b3 - b1);
    g_nfin[nb * PRE + r] = isfinite(sc) ? 1 : 0;
}

// ---------------- suppression bit-matrix ----------------
__global__ __launch_bounds__(64) void k_mask() {
    int bi = blockIdx.x, bj = blockIdx.y, nb = blockIdx.z;
    int t = threadIdx.x;
    int i = bi * 64 + t;
    __shared__ float sb[64][5];
    unsigned long long bits = 0;
    if (bj >= bi) {
        int jb = bj * 64 + t;
        if (jb < PRE) {
            const float* q = g_nbox + ((size_t)nb * PRE + jb) * 5;
            sb[t][0] = q[0]; sb[t][1] = q[1]; sb[t][2] = q[2];
            sb[t][3] = q[3]; sb[t][4] = q[4];
        }
        __syncthreads();
        if (i < PRE) {
            const float* pI = g_nbox + ((size_t)nb * PRE + i) * 5;
            float x0 = pI[0], y0 = pI[1], x1 = pI[2], y1 = pI[3], ar = pI[4];
            int jmax = min(64, PRE - bj * 64);
            for (int jj = 0; jj < jmax; ++jj) {
                int j = bj * 64 + jj;
                if (j <= i) continue;
                float xx1 = fmaxf(x0, sb[jj][0]);
                float yy1 = fmaxf(y0, sb[jj][1]);
                float xx2 = fminf(x1, sb[jj][2]);
                float yy2 = fminf(y1, sb[jj][3]);
                float inter = fmaxf(xx2 - xx1, 0.0f) * fmaxf(yy2 - yy1, 0.0f);
                float iou = inter / (ar + sb[jj][4] - inter + 1e-9f);
                if (iou > 0.7f) bits |= (1ULL << jj);
            }
        }
    }
    if (i < PRE) g_mask[((size_t)nb * PRE + i) * NW + bj] = bits;
}

// ---------------- sequential greedy scan, early-exit at 300 ----------------
__global__ __launch_bounds__(128) void k_scan(float* __restrict__ out) {
    int nb = blockIdx.x;
    __shared__ unsigned long long keep[NW];
    for (int w = threadIdx.x; w < NW; w += 128) {
        unsigned long long b = 0;
        for (int t = 0; t < 64; ++t) {
            int idx = w * 64 + t;
            if (idx < PRE && g_nfin[nb * PRE + idx]) b |= (1ULL << t);
        }
        keep[w] = b;
    }
    __syncthreads();
    int cnt = 0;
    for (int i = 0; i < PRE; ++i) {
        if ((keep[i >> 6] >> (i & 63)) & 1ULL) {
            if (threadIdx.x < 4)
                out[OUT_ROIS + ((size_t)nb * POST + cnt) * 4 + threadIdx.x] =
                    g_nbox[((size_t)nb * PRE + i) * 5 + threadIdx.x];
            ++cnt;
            if (cnt == POST) break;
            const unsigned long long* row = g_mask + ((size_t)nb * PRE + i) * NW;
            __syncthreads();  // all warps past reading bit i before we mutate
            for (int w = threadIdx.x; w < NW; w += 128) keep[w] &= ~row[w];
            __syncthreads();
        }
    }
    __syncthreads();
    for (int z = cnt * 4 + threadIdx.x; z < POST * 4; z += 128)
        out[OUT_ROIS + (size_t)nb * POST * 4 + z] = 0.0f;
}

// ---------------- launcher ----------------
extern "C" void kernel_launch(void* const* d_in, const int* in_sizes, int n_in,
                              void* d_out, int out_size) {
    const float* x  = (const float*)d_in[0];
    const float* w1 = (const float*)d_in[1];
    const float* b1 = (const float*)d_in[2];
    const float* sw = (const float*)d_in[3];
    const float* sb = (const float*)d_in[4];
    const float* lw = (const float*)d_in[5];
    const float* lb = (const float*)d_in[6];
    const void*  ph = d_in[7];
    const void*  pw = d_in[8];
    float* out = (float*)d_out;

    k_wT<<<(KTOT * COUT + 255) / 256, 256>>>(w1);
    k_anchor<<<(NANCH + 255) / 256, 256>>>(out);
    k_conv<<<dim3(30, 4, NB), 256>>>(x, b1);
    k_heads<<<dim3(30, NB), 128>>>(sw, sb, lw, lb, out);
    k_decode<<<dim3(SORTN / 256, NB), 256>>>(out, ph, pw);
    k_sort_local<<<dim3(16, NB), 512>>>();
    for (int k = 8192; k <= 65536; k <<= 1) {
        for (int j = k >> 1; j >= 4096; j >>= 1)
            k_sort_global<<<dim3(128, NB), 256>>>(k, j);
        k_sort_tail<<<dim3(16, NB), 512>>>(k);
    }
    k_gather<<<dim3((PRE + 255) / 256, NB), 256>>>();
    k_mask<<<dim3(NW, NW, NB), 64>>>();
    k_scan<<<NB, 128>>>(out);
}

// round 5
// speedup vs baseline: 1.3373x; 1.3373x over previous
#include <cuda_runtime.h>
#include <cuda_bf16.h>
#include <cstdint>
#include <math.h>

#define NB 8
#define CIN 512
#define COUT 512
#define HH 50
#define WW 76
#define HW 3800
#define NANCH 34200
#define KTOT 4608
#define PRE 6000
#define POST 300
#define SORTN 65536
#define NW 94

#define OUT_LOCS 0
#define OUT_SCORES 1094400
#define OUT_ROIS 1641600
#define OUT_ANCH 1651200

// ---------------- static scratch ----------------
__device__ __nv_bfloat16 g_wA0[COUT * KTOT];
__device__ __nv_bfloat16 g_wA1[COUT * KTOT];
__device__ __nv_bfloat16 g_wA2[COUT * KTOT];
__device__ __nv_bfloat16 g_xs0[(size_t)NB * HW * CIN];
__device__ __nv_bfloat16 g_xs1[(size_t)NB * HW * CIN];
__device__ __nv_bfloat16 g_xs2[(size_t)NB * HW * CIN];
__device__ float g_feat[(size_t)NB * COUT * HW];
__device__ float g_fg[NB * NANCH];
__device__ float g_boxes[(size_t)NB * NANCH * 4];
__device__ unsigned long long g_keys[(size_t)NB * SORTN];
__device__ float g_nbox[NB * PRE * 5];
__device__ unsigned char g_nfin[NB * PRE];
__device__ unsigned long long g_mask[(size_t)NB * PRE * NW];

// ---------------- helpers ----------------
__device__ __forceinline__ unsigned fenc(float f) {
    unsigned u = __float_as_uint(f);
    return (u & 0x80000000u) ? ~u : (u | 0x80000000u);
}
__device__ __forceinline__ float fdec(unsigned e) {
    return (e & 0x80000000u) ? __uint_as_float(e & 0x7FFFFFFFu)
                             : __uint_as_float(~e);
}
__device__ __forceinline__ float dimval(const void* p) {
    int v = *(const int*)p;
    if (v > 0 && v < 100000) return (float)v;
    return *(const float*)p;
}
__device__ __forceinline__ uint32_t smem_u32(const void* p) {
    uint32_t a;
    asm("{ .reg .u64 t; cvta.to.shared.u64 t, %1; cvt.u32.u64 %0, t; }"
        : "=r"(a) : "l"(p));
    return a;
}
__device__ __forceinline__ void cp16(uint32_t dst, const void* src) {
    asm volatile("cp.async.cg.shared.global [%0], [%1], 16;" :: "r"(dst), "l"(src));
}
__device__ __forceinline__ void cp16z(uint32_t dst, const void* src, int sz) {
    asm volatile("cp.async.cg.shared.global [%0], [%1], 16, %2;"
                 :: "r"(dst), "l"(src), "r"(sz));
}
__device__ __forceinline__ void ldm4(uint32_t* r, uint32_t addr) {
    asm volatile("ldmatrix.sync.aligned.m8n8.x4.shared.b16 {%0,%1,%2,%3}, [%4];"
                 : "=r"(r[0]), "=r"(r[1]), "=r"(r[2]), "=r"(r[3]) : "r"(addr));
}
__device__ __forceinline__ void mma16816(float* c, const uint32_t* a,
                                         uint32_t b0, uint32_t b1) {
    asm volatile(
        "mma.sync.aligned.m16n8k16.row.col.f32.bf16.bf16.f32 "
        "{%0,%1,%2,%3}, {%4,%5,%6,%7}, {%8,%9}, {%0,%1,%2,%3};"
        : "+f"(c[0]), "+f"(c[1]), "+f"(c[2]), "+f"(c[3])
        : "r"(a[0]), "r"(a[1]), "r"(a[2]), "r"(a[3]), "r"(b0), "r"(b1));
}

// ---------------- prep: split conv1 weights into 3 bf16 planes [cout][k] ----------------
__global__ void k_split_w(const float* __restrict__ w) {
    int idx = blockIdx.x * 256 + threadIdx.x;
    if (idx >= COUT * KTOT) return;
    int m = idx / KTOT;
    int k = idx - m * KTOT;
    int s = k >> 9, c = k & 511;
    float val = w[(((size_t)m * CIN + c) * 3 + s / 3) * 3 + s % 3];
    __nv_bfloat16 b0 = __float2bfloat16_rn(val);
    float r1 = val - __bfloat162float(b0);
    __nv_bfloat16 b1 = __float2bfloat16_rn(r1);
    float r2 = r1 - __bfloat162float(b1);
    __nv_bfloat16 b2 = __float2bfloat16_rn(r2);
    size_t o = (size_t)m * KTOT + k;
    g_wA0[o] = b0; g_wA1[o] = b1; g_wA2[o] = b2;
}

// ---------------- prep: transpose + split x into [b][p][c] bf16 planes ----------------
__global__ __launch_bounds__(1024) void k_split_x(const float* __restrict__ x) {
    __shared__ float tile[32][33];
    int nb = blockIdx.z;
    int p0 = blockIdx.x * 32, c0 = blockIdx.y * 32;
    int tx = threadIdx.x, ty = threadIdx.y;
    int p = p0 + tx;
    if (p < HW) tile[ty][tx] = x[((size_t)nb * CIN + c0 + ty) * HW + p];
    __syncthreads();
    p = p0 + ty;
    if (p >= HW) return;
    float val = tile[tx][ty];
    __nv_bfloat16 b0 = __float2bfloat16_rn(val);
    float r1 = val - __bfloat162float(b0);
    __nv_bfloat16 b1 = __float2bfloat16_rn(r1);
    float r2 = r1 - __bfloat162float(b1);
    __nv_bfloat16 b2 = __float2bfloat16_rn(r2);
    size_t o = ((size_t)nb * HW + p) * CIN + c0 + tx;
    g_xs0[o] = b0; g_xs1[o] = b1; g_xs2[o] = b2;
}

// ---------------- anchors ----------------
__global__ void k_anchor(float* __restrict__ out) {
    int i = blockIdx.x * 256 + threadIdx.x;
    if (i >= NANCH) return;
    int a = i % 9, p = i / 9;
    int y = p / WW, x = p % WW;
    int ri = a / 3, si = a % 3;
    const float rat[3] = {0.5f, 1.0f, 2.0f};
    const float scl[3] = {8.0f, 16.0f, 32.0f};
    float h = 16.0f * scl[si] * sqrtf(rat[ri]);
    float w = 16.0f * scl[si] * sqrtf(1.0f / rat[ri]);
    float bx0 = 8.0f - w * 0.5f, by0 = 8.0f - h * 0.5f;
    float bx1 = 8.0f + w * 0.5f, by1 = 8.0f + h * 0.5f;
    float sx = x * 16.0f, sy = y * 16.0f;
    float* o = out + OUT_ANCH + (size_t)i * 4;
    o[0] = sx + bx0; o[1] = sy + by0; o[2] = sx + bx1; o[3] = sy + by1;
}

// ---------------- conv via mma.sync bf16x3 (6-pass, split accumulators) ----------------
// accM: main pass w0*x0 only (4608 adds, fp32-parity error).
// accC: 5 correction passes (all <= 2^-9 magnitude; rounding negligible).
#define CHUNKS 72
#define PLANE 16384
#define BUFSZ 98304

__global__ __launch_bounds__(256, 1) void k_convh(const float* __restrict__ bias) {
    extern __shared__ char smem[];
    const int tid = threadIdx.x;
    const int lane = tid & 31, wid = tid >> 5;
    const int warp_m = wid >> 1, warp_n = wid & 1;
    const int nb = blockIdx.z, mtile = blockIdx.y * 128, n0 = blockIdx.x * 128;
    uint32_t sbase = smem_u32(smem);

    const __nv_bfloat16* wptr[3] = {g_wA0, g_wA1, g_wA2};
    const __nv_bfloat16* xptr[3] = {g_xs0, g_xs1, g_xs2};

    auto load_chunk = [&](int t, int buf) {
        int s = t >> 3, c0 = (t & 7) * 64;
        int dy = s / 3 - 1, dx = s % 3 - 1;
        uint32_t base = sbase + buf * BUFSZ;
#pragma unroll
        for (int it0 = 0; it0 < 12; ++it0) {
            int it = it0 * 256 + tid;
            int split = it >> 10, rem = it & 1023, r = rem >> 3, cq = rem & 7;
            const __nv_bfloat16* src = wptr[split] + (size_t)(mtile + r) * KTOT +
                                       s * 512 + c0 + cq * 8;
            uint32_t dst = base + split * PLANE + r * 128 + ((cq ^ (r & 7)) << 4);
            cp16(dst, src);
        }
#pragma unroll
        for (int it0 = 0; it0 < 12; ++it0) {
            int it = it0 * 256 + tid;
            int split = it >> 10, rem = it & 1023, r = rem >> 3, cq = rem & 7;
            int p = n0 + r;
            int py = p / WW, px = p - py * WW;
            int y2 = py + dy, x2 = px + dx;
            bool ok = (p < HW) && ((unsigned)y2 < (unsigned)HH) &&
                      ((unsigned)x2 < (unsigned)WW);
            int pp = ok ? (y2 * WW + x2) : 0;
            const __nv_bfloat16* src = xptr[split] + ((size_t)nb * HW + pp) * CIN +
                                       c0 + cq * 8;
            uint32_t dst = base + 49152 + split * PLANE + r * 128 +
                           ((cq ^ (r & 7)) << 4);
            cp16z(dst, src, ok ? 16 : 0);
        }
        asm volatile("cp.async.commit_group;");
    };

    float accM[2][8][4];
    float accC[2][8][4];
#pragma unroll
    for (int i = 0; i < 2; ++i)
#pragma unroll
        for (int j = 0; j < 8; ++j)
#pragma unroll
            for (int q = 0; q < 4; ++q) { accM[i][j][q] = 0.0f; accC[i][j][q] = 0.0f; }

    const int PA[6] = {0, 0, 1, 0, 1, 2};
    const int PB[6] = {0, 1, 0, 2, 1, 0};

    load_chunk(0, 0);
    for (int t = 0; t < CHUNKS; ++t) {
        if (t + 1 < CHUNKS) {
            load_chunk(t + 1, (t + 1) & 1);
            asm volatile("cp.async.wait_group 1;");
        } else {
            asm volatile("cp.async.wait_group 0;");
        }
        __syncthreads();
        uint32_t Ab = sbase + (t & 1) * BUFSZ;
        uint32_t Bb = Ab + 49152;
#pragma unroll
        for (int pass = 0; pass < 6; ++pass) {
            uint32_t As = Ab + PA[pass] * PLANE;
            uint32_t Bs = Bb + PB[pass] * PLANE;
            float (*acc)[8][4] = (pass == 0) ? accM : accC;
#pragma unroll
            for (int ks = 0; ks < 4; ++ks) {
                uint32_t a[2][4];
#pragma unroll
                for (int mt = 0; mt < 2; ++mt) {
                    int R = warp_m * 32 + mt * 16 + (lane & 15);
                    int kc = ks * 2 + (lane >> 4);
                    ldm4(a[mt], As + R * 128 + ((kc ^ (R & 7)) << 4));
                }
                uint32_t b[4][4];
#pragma unroll
                for (int g2 = 0; g2 < 4; ++g2) {
                    int R = warp_n * 64 + g2 * 16 + ((lane >> 4) * 8) + (lane & 7);
                    int kc = ks * 2 + ((lane >> 3) & 1);
                    ldm4(b[g2], Bs + R * 128 + ((kc ^ (R & 7)) << 4));
                }
#pragma unroll
                for (int mt = 0; mt < 2; ++mt)
#pragma unroll
                    for (int nt = 0; nt < 8; ++nt)
                        mma16816(acc[mt][nt], a[mt],
                                 b[nt >> 1][(nt & 1) * 2], b[nt >> 1][(nt & 1) * 2 + 1]);
            }
        }
        __syncthreads();
    }

    // epilogue: main + correction, bias + relu -> g_feat[n][m][p]
    int g = lane >> 2, t2 = (lane & 3) * 2;
#pragma unroll
    for (int mt = 0; mt < 2; ++mt) {
        int m0 = mtile + warp_m * 32 + mt * 16 + g;
        int m1 = m0 + 8;
        float bv0 = bias[m0], bv1 = bias[m1];
        float* d0 = g_feat + ((size_t)nb * COUT + m0) * HW;
        float* d1 = g_feat + ((size_t)nb * COUT + m1) * HW;
#pragma unroll
        for (int nt = 0; nt < 8; ++nt) {
            int p = n0 + warp_n * 64 + nt * 8 + t2;
            if (p < HW) {
                float2 v0, v1;
                v0.x = fmaxf((accM[mt][nt][0] + accC[mt][nt][0]) + bv0, 0.0f);
                v0.y = fmaxf((accM[mt][nt][1] + accC[mt][nt][1]) + bv0, 0.0f);
                v1.x = fmaxf((accM[mt][nt][2] + accC[mt][nt][2]) + bv1, 0.0f);
                v1.y = fmaxf((accM[mt][nt][3] + accC[mt][nt][3]) + bv1, 0.0f);
                *(float2*)(d0 + p) = v0;
                *(float2*)(d1 + p) = v1;
            }
        }
    }
}

// ---------------- heads: 1x1 convs + softmax ----------------
__global__ __launch_bounds__(128) void k_heads(const float* __restrict__ swg,
                                               const float* __restrict__ sb,
                                               const float* __restrict__ lwg,
                                               const float* __restrict__ lb,
                                               float* __restrict__ out) {
    int nb = blockIdx.y;
    int p = blockIdx.x * 128 + threadIdx.x;
    __shared__ float sw[128 * 54];
    float acc[54];
#pragma unroll
    for (int o = 0; o < 54; ++o) acc[o] = 0.0f;
    const float* feat = g_feat + (size_t)nb * COUT * HW;

    for (int c0 = 0; c0 < CIN; c0 += 128) {
        for (int t = threadIdx.x; t < 128 * 54; t += 128) {
            int cl = t / 54, o = t % 54;
            sw[t] = (o < 18) ? swg[o * CIN + c0 + cl] : lwg[(o - 18) * CIN + c0 + cl];
        }
        __syncthreads();
        if (p < HW) {
            for (int cl = 0; cl < 128; ++cl) {
                float f = feat[(size_t)(c0 + cl) * HW + p];
                const float* wrow = &sw[cl * 54];
#pragma unroll
                for (int o = 0; o < 54; ++o) acc[o] += wrow[o] * f;
            }
        }
        __syncthreads();
    }
    if (p >= HW) return;
#pragma unroll
    for (int a = 0; a < 9; ++a) {
        float s0 = acc[a * 2 + 0] + sb[a * 2 + 0];
        float s1 = acc[a * 2 + 1] + sb[a * 2 + 1];
        float m = fmaxf(s0, s1);
        float e0 = expf(s0 - m), e1 = expf(s1 - m);
        float fg = e1 / (e0 + e1);
        size_t ai = (size_t)nb * NANCH + (size_t)p * 9 + a;
        out[OUT_SCORES + ai * 2 + 0] = s0;
        out[OUT_SCORES + ai * 2 + 1] = s1;
        g_fg[ai] = fg;
        out[OUT_LOCS + ai * 4 + 0] = acc[18 + a * 4 + 0] + lb[a * 4 + 0];
        out[OUT_LOCS + ai * 4 + 1] = acc[18 + a * 4 + 1] + lb[a * 4 + 1];
        out[OUT_LOCS + ai * 4 + 2] = acc[18 + a * 4 + 2] + lb[a * 4 + 2];
        out[OUT_LOCS + ai * 4 + 3] = acc[18 + a * 4 + 3] + lb[a * 4 + 3];
    }
}

// ---------------- decode + keys ----------------
__global__ void k_decode(const float* __restrict__ out_ro,
                         const void* __restrict__ ph, const void* __restrict__ pw) {
    int nb = blockIdx.y;
    int i = blockIdx.x * 256 + threadIdx.x;
    if (i >= SORTN) return;
    unsigned long long key;
    if (i < NANCH) {
        float imH = dimval(ph), imW = dimval(pw);
        const float* an = out_ro + OUT_ANCH + (size_t)i * 4;
        size_t ai = (size_t)nb * NANCH + i;
        const float* lc = out_ro + OUT_LOCS + ai * 4;
        float ax0 = an[0], ay0 = an[1], ax1 = an[2], ay1 = an[3];
        float aw = ax1 - ax0, ah = ay1 - ay0;
        float actx = ax0 + 0.5f * aw, acty = ay0 + 0.5f * ah;
        float cx = lc[0] * aw + actx, cy = lc[1] * ah + acty;
        float w = expf(lc[2]) * aw, h = expf(lc[3]) * ah;
        float b0 = cx - 0.5f * w, b1 = cy - 0.5f * h;
        float b2 = cx + 0.5f * w, b3 = cy + 0.5f * h;
        b0 = fminf(fmaxf(b0, 0.0f), imW);
        b2 = fminf(fmaxf(b2, 0.0f), imW);
        b1 = fminf(fmaxf(b1, 0.0f), imH);
        b3 = fminf(fmaxf(b3, 0.0f), imH);
        bool valid = ((b2 - b0) >= 16.0f) && ((b3 - b1) >= 16.0f);
        float sc = valid ? g_fg[ai] : -INFINITY;
        float* bx = g_boxes + ai * 4;
        bx[0] = b0; bx[1] = b1; bx[2] = b2; bx[3] = b3;
        key = ((unsigned long long)(~fenc(sc)) << 32) | (unsigned)i;
    } else {
        key = ~0ULL;
    }
    g_keys[(size_t)nb * SORTN + i] = key;
}

// ---------------- bitonic sort ----------------
__global__ __launch_bounds__(512) void k_sort_local() {
    __shared__ unsigned long long sk[4096];
    int nb = blockIdx.y;
    int base = blockIdx.x * 4096;
    unsigned long long* gk = g_keys + (size_t)nb * SORTN;
    for (int t = threadIdx.x; t < 4096; t += 512) sk[t] = gk[base + t];
    __syncthreads();
    for (int k = 2; k <= 4096; k <<= 1) {
        for (int j = k >> 1; j > 0; j >>= 1) {
#pragma unroll 4
            for (int q = 0; q < 4; ++q) {
                int l = q * 512 + threadIdx.x;
                int i = ((l & ~(j - 1)) << 1) | (l & (j - 1));
                bool asc = (((base + i) & k) == 0);
                unsigned long long a = sk[i], b = sk[i + j];
                bool swp = asc ? (a > b) : (a < b);
                if (swp) { sk[i] = b; sk[i + j] = a; }
            }
            __syncthreads();
        }
    }
    for (int t = threadIdx.x; t < 4096; t += 512) gk[base + t] = sk[t];
}

__global__ void k_sort_global(int k, int j) {
    int nb = blockIdx.y;
    int l = blockIdx.x * 256 + threadIdx.x;
    unsigned long long* gk = g_keys + (size_t)nb * SORTN;
    int i = ((l & ~(j - 1)) << 1) | (l & (j - 1));
    bool asc = ((i & k) == 0);
    unsigned long long a = gk[i], b = gk[i + j];
    bool swp = asc ? (a > b) : (a < b);
    if (swp) { gk[i] = b; gk[i + j] = a; }
}

__global__ __launch_bounds__(512) void k_sort_tail(int k) {
    __shared__ unsigned long long sk[4096];
    int nb = blockIdx.y;
    int base = blockIdx.x * 4096;
    unsigned long long* gk = g_keys + (size_t)nb * SORTN;
    for (int t = threadIdx.x; t < 4096; t += 512) sk[t] = gk[base + t];
    __syncthreads();
    for (int j = 2048; j > 0; j >>= 1) {
#pragma unroll 4
        for (int q = 0; q < 4; ++q) {
            int l = q * 512 + threadIdx.x;
            int i = ((l & ~(j - 1)) << 1) | (l & (j - 1));
            bool asc = (((base + i) & k) == 0);
            unsigned long long a = sk[i], b = sk[i + j];
            bool swp = asc ? (a > b) : (a < b);
            if (swp) { sk[i] = b; sk[i + j] = a; }
        }
        __syncthreads();
    }
    for (int t = threadIdx.x; t < 4096; t += 512) gk[base + t] = sk[t];
}

// ---------------- gather top-6000 ----------------
__global__ void k_gather() {
    int nb = blockIdx.y;
    int r = blockIdx.x * 256 + threadIdx.x;
    if (r >= PRE) return;
    unsigned long long key = g_keys[(size_t)nb * SORTN + r];
    unsigned idx = (unsigned)(key & 0xFFFFFFFFu);
    unsigned hi = (unsigned)(key >> 32);
    float sc = fdec(~hi);
    const float* bx = g_boxes + ((size_t)nb * NANCH + idx) * 4;
    float b0 = bx[0], b1 = bx[1], b2 = bx[2], b3 = bx[3];
    float* dst = g_nbox + ((size_t)nb * PRE + r) * 5;
    dst[0] = b0; dst[1] = b1; dst[2] = b2; dst[3] = b3;
    dst[4] = (b2 - b0) * (b3 - b1);
    g_nfin[nb * PRE + r] = isfinite(sc) ? 1 : 0;
}

// ---------------- suppression bit-matrix ----------------
__global__ __launch_bounds__(64) void k_mask() {
    int bi = blockIdx.x, bj = blockIdx.y, nb = blockIdx.z;
    int t = threadIdx.x;
    int i = bi * 64 + t;
    __shared__ float sb[64][5];
    unsigned long long bits = 0;
    if (bj >= bi) {
        int jb = bj * 64 + t;
        if (jb < PRE) {
            const float* q = g_nbox + ((size_t)nb * PRE + jb) * 5;
            sb[t][0] = q[0]; sb[t][1] = q[1]; sb[t][2] = q[2];
            sb[t][3] = q[3]; sb[t][4] = q[4];
        }
        __syncthreads();
        if (i < PRE) {
            const float* pI = g_nbox + ((size_t)nb * PRE + i) * 5;
            float x0 = pI[0], y0 = pI[1], x1 = pI[2], y1 = pI[3], ar = pI[4];
            int jmax = min(64, PRE - bj * 64);
            for (int jj = 0; jj < jmax; ++jj) {
                int j = bj * 64 + jj;
                if (j <= i) continue;
                float xx1 = fmaxf(x0, sb[jj][0]);
                float yy1 = fmaxf(y0, sb[jj][1]);
                float xx2 = fminf(x1, sb[jj][2]);
                float yy2 = fminf(y1, sb[jj][3]);
                float inter = fmaxf(xx2 - xx1, 0.0f) * fmaxf(yy2 - yy1, 0.0f);
                float iou = inter / (ar + sb[jj][4] - inter + 1e-9f);
                if (iou > 0.7f) bits |= (1ULL << jj);
            }
        }
    }
    if (i < PRE) g_mask[((size_t)nb * PRE + i) * NW + bj] = bits;
}

// ---------------- sequential greedy scan, early-exit at 300 ----------------
__global__ __launch_bounds__(128) void k_scan(float* __restrict__ out) {
    int nb = blockIdx.x;
    __shared__ unsigned long long keep[NW];
    for (int w = threadIdx.x; w < NW; w += 128) {
        unsigned long long b = 0;
        for (int t = 0; t < 64; ++t) {
            int idx = w * 64 + t;
            if (idx < PRE && g_nfin[nb * PRE + idx]) b |= (1ULL << t);
        }
        keep[w] = b;
    }
    __syncthreads();
    int cnt = 0;
    for (int i = 0; i < PRE; ++i) {
        if ((keep[i >> 6] >> (i & 63)) & 1ULL) {
            if (threadIdx.x < 4)
                out[OUT_ROIS + ((size_t)nb * POST + cnt) * 4 + threadIdx.x] =
                    g_nbox[((size_t)nb * PRE + i) * 5 + threadIdx.x];
            ++cnt;
            if (cnt == POST) break;
            const unsigned long long* row = g_mask + ((size_t)nb * PRE + i) * NW;
            __syncthreads();
            for (int w = threadIdx.x; w < NW; w += 128) keep[w] &= ~row[w];
            __syncthreads();
        }
    }
    __syncthreads();
    for (int z = cnt * 4 + threadIdx.x; z < POST * 4; z += 128)
        out[OUT_ROIS + (size_t)nb * POST * 4 + z] = 0.0f;
}

// ---------------- launcher ----------------
extern "C" void kernel_launch(void* const* d_in, const int* in_sizes, int n_in,
                              void* d_out, int out_size) {
    const float* x  = (const float*)d_in[0];
    const float* w1 = (const float*)d_in[1];
    const float* b1 = (const float*)d_in[2];
    const float* sw = (const float*)d_in[3];
    const float* sb = (const float*)d_in[4];
    const float* lw = (const float*)d_in[5];
    const float* lb = (const float*)d_in[6];
    const void*  ph = d_in[7];
    const void*  pw = d_in[8];
    float* out = (float*)d_out;

    cudaFuncSetAttribute(k_convh, cudaFuncAttributeMaxDynamicSharedMemorySize,
                         2 * BUFSZ);

    k_split_w<<<(COUT * KTOT + 255) / 256, 256>>>(w1);
    k_split_x<<<dim3(119, 16, NB), dim3(32, 32)>>>(x);
    k_anchor<<<(NANCH + 255) / 256, 256>>>(out);
    k_convh<<<dim3(30, 4, NB), 256, 2 * BUFSZ>>>(b1);
    k_heads<<<dim3(30, NB), 128>>>(sw, sb, lw, lb, out);
    k_decode<<<dim3(SORTN / 256, NB), 256>>>(out, ph, pw);
    k_sort_local<<<dim3(16, NB), 512>>>();
    for (int k = 8192; k <= 65536; k <<= 1) {
        for (int j = k >> 1; j >= 4096; j >>= 1)
            k_sort_global<<<dim3(128, NB), 256>>>(k, j);
        k_sort_tail<<<dim3(16, NB), 512>>>(k);
    }
    k_gather<<<dim3((PRE + 255) / 256, NB), 256>>>();
    k_mask<<<dim3(NW, NW, NB), 64>>>();
    k_scan<<<NB, 128>>>(out);
}

// round 6
// speedup vs baseline: 2.2575x; 1.6880x over previous
#include <cuda_runtime.h>
#include <cuda_fp16.h>
#include <cstdint>
#include <math.h>

#define NB 8
#define CIN 512
#define COUT 512
#define HH 50
#define WW 76
#define HW 3800
#define NANCH 34200
#define KTOT 4608
#define PRE 6000
#define POST 300
#define SORTN 65536
#define NW 94

#define OUT_LOCS 0
#define OUT_SCORES 1094400
#define OUT_ROIS 1641600
#define OUT_ANCH 1651200

// ---------------- static scratch ----------------
__device__ __half g_wA0[COUT * KTOT];
__device__ __half g_wA1[COUT * KTOT];          // (w - w0) * 2^11
__device__ __half g_xs0[(size_t)NB * HW * CIN];
__device__ __half g_xs1[(size_t)NB * HW * CIN]; // (x - x0) * 2^11
__device__ float g_feat[(size_t)NB * COUT * HW];
__device__ float g_fg[NB * NANCH];
__device__ float g_boxes[(size_t)NB * NANCH * 4];
__device__ unsigned long long g_keys[(size_t)NB * SORTN];
__device__ float g_nbox[NB * PRE * 5];
__device__ unsigned char g_nfin[NB * PRE];
__device__ unsigned long long g_mask[(size_t)NB * PRE * NW];

// ---------------- helpers ----------------
__device__ __forceinline__ unsigned fenc(float f) {
    unsigned u = __float_as_uint(f);
    return (u & 0x80000000u) ? ~u : (u | 0x80000000u);
}
__device__ __forceinline__ float fdec(unsigned e) {
    return (e & 0x80000000u) ? __uint_as_float(e & 0x7FFFFFFFu)
                             : __uint_as_float(~e);
}
__device__ __forceinline__ float dimval(const void* p) {
    int v = *(const int*)p;
    if (v > 0 && v < 100000) return (float)v;
    return *(const float*)p;
}
__device__ __forceinline__ uint32_t smem_u32(const void* p) {
    uint32_t a;
    asm("{ .reg .u64 t; cvta.to.shared.u64 t, %1; cvt.u32.u64 %0, t; }"
        : "=r"(a) : "l"(p));
    return a;
}
__device__ __forceinline__ void cp16(uint32_t dst, const void* src) {
    asm volatile("cp.async.cg.shared.global [%0], [%1], 16;" :: "r"(dst), "l"(src));
}
__device__ __forceinline__ void cp16z(uint32_t dst, const void* src, int sz) {
    asm volatile("cp.async.cg.shared.global [%0], [%1], 16, %2;"
                 :: "r"(dst), "l"(src), "r"(sz));
}
__device__ __forceinline__ void ldm4(uint32_t* r, uint32_t addr) {
    asm volatile("ldmatrix.sync.aligned.m8n8.x4.shared.b16 {%0,%1,%2,%3}, [%4];"
                 : "=r"(r[0]), "=r"(r[1]), "=r"(r[2]), "=r"(r[3]) : "r"(addr));
}
__device__ __forceinline__ void mma16816(float* c, const uint32_t* a,
                                         uint32_t b0, uint32_t b1) {
    asm volatile(
        "mma.sync.aligned.m16n8k16.row.col.f32.f16.f16.f32 "
        "{%0,%1,%2,%3}, {%4,%5,%6,%7}, {%8,%9}, {%0,%1,%2,%3};"
        : "+f"(c[0]), "+f"(c[1]), "+f"(c[2]), "+f"(c[3])
        : "r"(a[0]), "r"(a[1]), "r"(a[2]), "r"(a[3]), "r"(b0), "r"(b1));
}

// ---------------- prep: 2-way scaled fp16 split of conv1 weights [cout][k] ----------------
__global__ void k_split_w(const float* __restrict__ w) {
    int idx = blockIdx.x * 256 + threadIdx.x;
    if (idx >= COUT * KTOT) return;
    int m = idx / KTOT;
    int k = idx - m * KTOT;
    int s = k >> 9, c = k & 511;
    float val = w[(((size_t)m * CIN + c) * 3 + s / 3) * 3 + s % 3];
    __half h0 = __float2half_rn(val);
    float r1 = val - __half2float(h0);
    __half h1 = __float2half_rn(r1 * 2048.0f);
    size_t o = (size_t)m * KTOT + k;
    g_wA0[o] = h0; g_wA1[o] = h1;
}

// ---------------- prep: transpose + scaled split x into [b][p][c] ----------------
__global__ __launch_bounds__(1024) void k_split_x(const float* __restrict__ x) {
    __shared__ float tile[32][33];
    int nb = blockIdx.z;
    int p0 = blockIdx.x * 32, c0 = blockIdx.y * 32;
    int tx = threadIdx.x, ty = threadIdx.y;
    int p = p0 + tx;
    if (p < HW) tile[ty][tx] = x[((size_t)nb * CIN + c0 + ty) * HW + p];
    __syncthreads();
    p = p0 + ty;
    if (p >= HW) return;
    float val = tile[tx][ty];
    __half h0 = __float2half_rn(val);
    float r1 = val - __half2float(h0);
    __half h1 = __float2half_rn(r1 * 2048.0f);
    size_t o = ((size_t)nb * HW + p) * CIN + c0 + tx;
    g_xs0[o] = h0; g_xs1[o] = h1;
}

// ---------------- anchors ----------------
__global__ void k_anchor(float* __restrict__ out) {
    int i = blockIdx.x * 256 + threadIdx.x;
    if (i >= NANCH) return;
    int a = i % 9, p = i / 9;
    int y = p / WW, x = p % WW;
    int ri = a / 3, si = a % 3;
    const float rat[3] = {0.5f, 1.0f, 2.0f};
    const float scl[3] = {8.0f, 16.0f, 32.0f};
    float h = 16.0f * scl[si] * sqrtf(rat[ri]);
    float w = 16.0f * scl[si] * sqrtf(1.0f / rat[ri]);
    float bx0 = 8.0f - w * 0.5f, by0 = 8.0f - h * 0.5f;
    float bx1 = 8.0f + w * 0.5f, by1 = 8.0f + h * 0.5f;
    float sx = x * 16.0f, sy = y * 16.0f;
    float* o = out + OUT_ANCH + (size_t)i * 4;
    o[0] = sx + bx0; o[1] = sy + by0; o[2] = sx + bx1; o[3] = sy + by1;
}

// ---------------- conv: mma.sync fp16 2-way scaled split, 3 passes ----------------
// CTA 128x128, 512 thr, 16 warps 4x4, warp tile 32x32.
// Passes: w0*x0 -> accM ; w0*x1s -> accC ; w1s*x0 -> accC.
// result = accM + accC * 2^-11.
#define CHUNKS 72
#define PLANE 16384
#define BUFSZ 65536
#define INVSC 4.8828125e-4f  /* 2^-11 */

__global__ __launch_bounds__(512, 1) void k_convh(const float* __restrict__ bias) {
    extern __shared__ char smem[];
    const int tid = threadIdx.x;
    const int lane = tid & 31, wid = tid >> 5;
    const int warp_m = wid & 3, warp_n = wid >> 2;
    const int nb = blockIdx.z, mtile = blockIdx.y * 128, n0 = blockIdx.x * 128;
    uint32_t sbase = smem_u32(smem);

    const __half* wptr[2] = {g_wA0, g_wA1};
    const __half* xptr[2] = {g_xs0, g_xs1};

    auto load_chunk = [&](int t, int buf) {
        int s = t >> 3, c0 = (t & 7) * 64;
        int dy = s / 3 - 1, dx = s % 3 - 1;
        uint32_t base = sbase + buf * BUFSZ;
#pragma unroll
        for (int it0 = 0; it0 < 4; ++it0) {
            int it = it0 * 512 + tid;
            int split = it >> 10, rem = it & 1023, r = rem >> 3, cq = rem & 7;
            const __half* src = wptr[split] + (size_t)(mtile + r) * KTOT +
                                s * 512 + c0 + cq * 8;
            uint32_t dst = base + split * PLANE + r * 128 + ((cq ^ (r & 7)) << 4);
            cp16(dst, src);
        }
#pragma unroll
        for (int it0 = 0; it0 < 4; ++it0) {
            int it = it0 * 512 + tid;
            int split = it >> 10, rem = it & 1023, r = rem >> 3, cq = rem & 7;
            int p = n0 + r;
            int py = p / WW, px = p - py * WW;
            int y2 = py + dy, x2 = px + dx;
            bool ok = (p < HW) && ((unsigned)y2 < (unsigned)HH) &&
                      ((unsigned)x2 < (unsigned)WW);
            int pp = ok ? (y2 * WW + x2) : 0;
            const __half* src = xptr[split] + ((size_t)nb * HW + pp) * CIN +
                                c0 + cq * 8;
            uint32_t dst = base + 32768 + split * PLANE + r * 128 +
                           ((cq ^ (r & 7)) << 4);
            cp16z(dst, src, ok ? 16 : 0);
        }
        asm volatile("cp.async.commit_group;");
    };

    float accM[2][4][4];
    float accC[2][4][4];
#pragma unroll
    for (int i = 0; i < 2; ++i)
#pragma unroll
        for (int j = 0; j < 4; ++j)
#pragma unroll
            for (int q = 0; q < 4; ++q) { accM[i][j][q] = 0.0f; accC[i][j][q] = 0.0f; }

    load_chunk(0, 0);
    for (int t = 0; t < CHUNKS; ++t) {
        if (t + 1 < CHUNKS) {
            load_chunk(t + 1, (t + 1) & 1);
            asm volatile("cp.async.wait_group 1;");
        } else {
            asm volatile("cp.async.wait_group 0;");
        }
        __syncthreads();
        uint32_t base = sbase + (t & 1) * BUFSZ;
        uint32_t A0 = base, A1 = base + PLANE;
        uint32_t B0 = base + 32768, B1 = base + 32768 + PLANE;
#pragma unroll
        for (int ks = 0; ks < 4; ++ks) {
            int kcA = ks * 2 + (lane >> 4);
            int kcB = ks * 2 + ((lane >> 3) & 1);
            uint32_t a0[2][4], a1[2][4], bb[2][4];
#pragma unroll
            for (int mt = 0; mt < 2; ++mt) {
                int R = warp_m * 32 + mt * 16 + (lane & 15);
                ldm4(a0[mt], A0 + R * 128 + ((kcA ^ (R & 7)) << 4));
            }
#pragma unroll
            for (int g2 = 0; g2 < 2; ++g2) {
                int R = warp_n * 32 + g2 * 16 + ((lane >> 4) * 8) + (lane & 7);
                ldm4(bb[g2], B0 + R * 128 + ((kcB ^ (R & 7)) << 4));
            }
#pragma unroll
            for (int mt = 0; mt < 2; ++mt)
#pragma unroll
                for (int nt = 0; nt < 4; ++nt)
                    mma16816(accM[mt][nt], a0[mt],
                             bb[nt >> 1][(nt & 1) * 2], bb[nt >> 1][(nt & 1) * 2 + 1]);
#pragma unroll
            for (int mt = 0; mt < 2; ++mt) {
                int R = warp_m * 32 + mt * 16 + (lane & 15);
                ldm4(a1[mt], A1 + R * 128 + ((kcA ^ (R & 7)) << 4));
            }
#pragma unroll
            for (int mt = 0; mt < 2; ++mt)
#pragma unroll
                for (int nt = 0; nt < 4; ++nt)
                    mma16816(accC[mt][nt], a1[mt],
                             bb[nt >> 1][(nt & 1) * 2], bb[nt >> 1][(nt & 1) * 2 + 1]);
#pragma unroll
            for (int g2 = 0; g2 < 2; ++g2) {
                int R = warp_n * 32 + g2 * 16 + ((lane >> 4) * 8) + (lane & 7);
                ldm4(bb[g2], B1 + R * 128 + ((kcB ^ (R & 7)) << 4));
            }
#pragma unroll
            for (int mt = 0; mt < 2; ++mt)
#pragma unroll
                for (int nt = 0; nt < 4; ++nt)
                    mma16816(accC[mt][nt], a0[mt],
                             bb[nt >> 1][(nt & 1) * 2], bb[nt >> 1][(nt & 1) * 2 + 1]);
        }
        __syncthreads();
    }

    // epilogue: accM + accC*2^-11 + bias, relu -> g_feat[n][m][p]
    int g = lane >> 2, t2 = (lane & 3) * 2;
#pragma unroll
    for (int mt = 0; mt < 2; ++mt) {
        int m0 = mtile + warp_m * 32 + mt * 16 + g;
        int m1 = m0 + 8;
        float bv0 = bias[m0], bv1 = bias[m1];
        float* d0 = g_feat + ((size_t)nb * COUT + m0) * HW;
        float* d1 = g_feat + ((size_t)nb * COUT + m1) * HW;
#pragma unroll
        for (int nt = 0; nt < 4; ++nt) {
            int p = n0 + warp_n * 32 + nt * 8 + t2;
            if (p < HW) {
                float2 v0, v1;
                v0.x = fmaxf(fmaf(accC[mt][nt][0], INVSC, accM[mt][nt][0]) + bv0, 0.0f);
                v0.y = fmaxf(fmaf(accC[mt][nt][1], INVSC, accM[mt][nt][1]) + bv0, 0.0f);
                v1.x = fmaxf(fmaf(accC[mt][nt][2], INVSC, accM[mt][nt][2]) + bv1, 0.0f);
                v1.y = fmaxf(fmaf(accC[mt][nt][3], INVSC, accM[mt][nt][3]) + bv1, 0.0f);
                *(float2*)(d0 + p) = v0;
                *(float2*)(d1 + p) = v1;
            }
        }
    }
}

// ---------------- heads: 1x1 convs + softmax (2 positions/thread) ----------------
__global__ __launch_bounds__(128) void k_heads(const float* __restrict__ swg,
                                               const float* __restrict__ sb,
                                               const float* __restrict__ lwg,
                                               const float* __restrict__ lb,
                                               float* __restrict__ out) {
    int nb = blockIdx.y;
    int p0 = blockIdx.x * 256 + threadIdx.x * 2;
    __shared__ float sw[128 * 54];
    float accA[54], accB[54];
#pragma unroll
    for (int o = 0; o < 54; ++o) { accA[o] = 0.0f; accB[o] = 0.0f; }
    const float* feat = g_feat + (size_t)nb * COUT * HW;

    for (int c0 = 0; c0 < CIN; c0 += 128) {
        for (int t = threadIdx.x; t < 128 * 54; t += 128) {
            int cl = t / 54, o = t % 54;
            sw[t] = (o < 18) ? swg[o * CIN + c0 + cl] : lwg[(o - 18) * CIN + c0 + cl];
        }
        __syncthreads();
        if (p0 < HW) {
            for (int cl = 0; cl < 128; ++cl) {
                float2 f = *(const float2*)(feat + (size_t)(c0 + cl) * HW + p0);
                const float* wrow = &sw[cl * 54];
#pragma unroll
                for (int o = 0; o < 54; ++o) {
                    accA[o] = fmaf(wrow[o], f.x, accA[o]);
                    accB[o] = fmaf(wrow[o], f.y, accB[o]);
                }
            }
        }
        __syncthreads();
    }
    if (p0 >= HW) return;
#pragma unroll
    for (int pp = 0; pp < 2; ++pp) {
        int p = p0 + pp;
        const float* acc = pp ? accB : accA;
#pragma unroll
        for (int a = 0; a < 9; ++a) {
            float s0 = acc[a * 2 + 0] + sb[a * 2 + 0];
            float s1 = acc[a * 2 + 1] + sb[a * 2 + 1];
            float m = fmaxf(s0, s1);
            float e0 = expf(s0 - m), e1 = expf(s1 - m);
            float fg = e1 / (e0 + e1);
            size_t ai = (size_t)nb * NANCH + (size_t)p * 9 + a;
            out[OUT_SCORES + ai * 2 + 0] = s0;
            out[OUT_SCORES + ai * 2 + 1] = s1;
            g_fg[ai] = fg;
            out[OUT_LOCS + ai * 4 + 0] = acc[18 + a * 4 + 0] + lb[a * 4 + 0];
            out[OUT_LOCS + ai * 4 + 1] = acc[18 + a * 4 + 1] + lb[a * 4 + 1];
            out[OUT_LOCS + ai * 4 + 2] = acc[18 + a * 4 + 2] + lb[a * 4 + 2];
            out[OUT_LOCS + ai * 4 + 3] = acc[18 + a * 4 + 3] + lb[a * 4 + 3];
        }
    }
}

// ---------------- decode + keys ----------------
__global__ void k_decode(const float* __restrict__ out_ro,
                         const void* __restrict__ ph, const void* __restrict__ pw) {
    int nb = blockIdx.y;
    int i = blockIdx.x * 256 + threadIdx.x;
    if (i >= SORTN) return;
    unsigned long long key;
    if (i < NANCH) {
        float imH = dimval(ph), imW = dimval(pw);
        const float* an = out_ro + OUT_ANCH + (size_t)i * 4;
        size_t ai = (size_t)nb * NANCH + i;
        const float* lc = out_ro + OUT_LOCS + ai * 4;
        float ax0 = an[0], ay0 = an[1], ax1 = an[2], ay1 = an[3];
        float aw = ax1 - ax0, ah = ay1 - ay0;
        float actx = ax0 + 0.5f * aw, acty = ay0 + 0.5f * ah;
        float cx = lc[0] * aw + actx, cy = lc[1] * ah + acty;
        float w = expf(lc[2]) * aw, h = expf(lc[3]) * ah;
        float b0 = cx - 0.5f * w, b1 = cy - 0.5f * h;
        float b2 = cx + 0.5f * w, b3 = cy + 0.5f * h;
        b0 = fminf(fmaxf(b0, 0.0f), imW);
        b2 = fminf(fmaxf(b2, 0.0f), imW);
        b1 = fminf(fmaxf(b1, 0.0f), imH);
        b3 = fminf(fmaxf(b3, 0.0f), imH);
        bool valid = ((b2 - b0) >= 16.0f) && ((b3 - b1) >= 16.0f);
        float sc = valid ? g_fg[ai] : -INFINITY;
        float* bx = g_boxes + ai * 4;
        bx[0] = b0; bx[1] = b1; bx[2] = b2; bx[3] = b3;
        key = ((unsigned long long)(~fenc(sc)) << 32) | (unsigned)i;
    } else {
        key = ~0ULL;
    }
    g_keys[(size_t)nb * SORTN + i] = key;
}

// ---------------- bitonic sort ----------------
__global__ __launch_bounds__(512) void k_sort_local() {
    __shared__ unsigned long long sk[4096];
    int nb = blockIdx.y;
    int base = blockIdx.x * 4096;
    unsigned long long* gk = g_keys + (size_t)nb * SORTN;
    for (int t = threadIdx.x; t < 4096; t += 512) sk[t] = gk[base + t];
    __syncthreads();
    for (int k = 2; k <= 4096; k <<= 1) {
        for (int j = k >> 1; j > 0; j >>= 1) {
#pragma unroll 4
            for (int q = 0; q < 4; ++q) {
                int l = q * 512 + threadIdx.x;
                int i = ((l & ~(j - 1)) << 1) | (l & (j - 1));
                bool asc = (((base + i) & k) == 0);
                unsigned long long a = sk[i], b = sk[i + j];
                bool swp = asc ? (a > b) : (a < b);
                if (swp) { sk[i] = b; sk[i + j] = a; }
            }
            __syncthreads();
        }
    }
    for (int t = threadIdx.x; t < 4096; t += 512) gk[base + t] = sk[t];
}

__global__ void k_sort_global(int k, int j) {
    int nb = blockIdx.y;
    int l = blockIdx.x * 256 + threadIdx.x;
    unsigned long long* gk = g_keys + (size_t)nb * SORTN;
    int i = ((l & ~(j - 1)) << 1) | (l & (j - 1));
    bool asc = ((i & k) == 0);
    unsigned long long a = gk[i], b = gk[i + j];
    bool swp = asc ? (a > b) : (a < b);
    if (swp) { gk[i] = b; gk[i + j] = a; }
}

__global__ __launch_bounds__(512) void k_sort_tail(int k) {
    __shared__ unsigned long long sk[4096];
    int nb = blockIdx.y;
    int base = blockIdx.x * 4096;
    unsigned long long* gk = g_keys + (size_t)nb * SORTN;
    for (int t = threadIdx.x; t < 4096; t += 512) sk[t] = gk[base + t];
    __syncthreads();
    for (int j = 2048; j > 0; j >>= 1) {
#pragma unroll 4
        for (int q = 0; q < 4; ++q) {
            int l = q * 512 + threadIdx.x;
            int i = ((l & ~(j - 1)) << 1) | (l & (j - 1));
            bool asc = (((base + i) & k) == 0);
            unsigned long long a = sk[i], b = sk[i + j];
            bool swp = asc ? (a > b) : (a < b);
            if (swp) { sk[i] = b; sk[i + j] = a; }
        }
        __syncthreads();
    }
    for (int t = threadIdx.x; t < 4096; t += 512) gk[base + t] = sk[t];
}

// ---------------- gather top-6000 ----------------
__global__ void k_gather() {
    int nb = blockIdx.y;
    int r = blockIdx.x * 256 + threadIdx.x;
    if (r >= PRE) return;
    unsigned long long key = g_keys[(size_t)nb * SORTN + r];
    unsigned idx = (unsigned)(key & 0xFFFFFFFFu);
    unsigned hi = (unsigned)(key >> 32);
    float sc = fdec(~hi);
    const float* bx = g_boxes + ((size_t)nb * NANCH + idx) * 4;
    float b0 = bx[0], b1 = bx[1], b2 = bx[2], b3 = bx[3];
    float* dst = g_nbox + ((size_t)nb * PRE + r) * 5;
    dst[0] = b0; dst[1] = b1; dst[2] = b2; dst[3] = b3;
    dst[4] = (b2 - b0) * (b3 - b1);
    g_nfin[nb * PRE + r] = isfinite(sc) ? 1 : 0;
}

// ---------------- suppression bit-matrix ----------------
__global__ __launch_bounds__(64) void k_mask() {
    int bi = blockIdx.x, bj = blockIdx.y, nb = blockIdx.z;
    int t = threadIdx.x;
    int i = bi * 64 + t;
    __shared__ float sb[64][5];
    unsigned long long bits = 0;
    if (bj >= bi) {
        int jb = bj * 64 + t;
        if (jb < PRE) {
            const float* q = g_nbox + ((size_t)nb * PRE + jb) * 5;
            sb[t][0] = q[0]; sb[t][1] = q[1]; sb[t][2] = q[2];
            sb[t][3] = q[3]; sb[t][4] = q[4];
        }
        __syncthreads();
        if (i < PRE) {
            const float* pI = g_nbox + ((size_t)nb * PRE + i) * 5;
            float x0 = pI[0], y0 = pI[1], x1 = pI[2], y1 = pI[3], ar = pI[4];
            int jmax = min(64, PRE - bj * 64);
            for (int jj = 0; jj < jmax; ++jj) {
                int j = bj * 64 + jj;
                if (j <= i) continue;
                float xx1 = fmaxf(x0, sb[jj][0]);
                float yy1 = fmaxf(y0, sb[jj][1]);
                float xx2 = fminf(x1, sb[jj][2]);
                float yy2 = fminf(y1, sb[jj][3]);
                float inter = fmaxf(xx2 - xx1, 0.0f) * fmaxf(yy2 - yy1, 0.0f);
                float iou = inter / (ar + sb[jj][4] - inter + 1e-9f);
                if (iou > 0.7f) bits |= (1ULL << jj);
            }
        }
    }
    if (i < PRE) g_mask[((size_t)nb * PRE + i) * NW + bj] = bits;
}

// ---------------- sequential greedy scan, early-exit at 300 ----------------
__global__ __launch_bounds__(128) void k_scan(float* __restrict__ out) {
    int nb = blockIdx.x;
    __shared__ unsigned long long keep[NW];
    for (int w = threadIdx.x; w < NW; w += 128) {
        unsigned long long b = 0;
        for (int t = 0; t < 64; ++t) {
            int idx = w * 64 + t;
            if (idx < PRE && g_nfin[nb * PRE + idx]) b |= (1ULL << t);
        }
        keep[w] = b;
    }
    __syncthreads();
    int cnt = 0;
    for (int i = 0; i < PRE; ++i) {
        if ((keep[i >> 6] >> (i & 63)) & 1ULL) {
            if (threadIdx.x < 4)
                out[OUT_ROIS + ((size_t)nb * POST + cnt) * 4 + threadIdx.x] =
                    g_nbox[((size_t)nb * PRE + i) * 5 + threadIdx.x];
            ++cnt;
            if (cnt == POST) break;
            const unsigned long long* row = g_mask + ((size_t)nb * PRE + i) * NW;
            __syncthreads();
            for (int w = threadIdx.x; w < NW; w += 128) keep[w] &= ~row[w];
            __syncthreads();
        }
    }
    __syncthreads();
    for (int z = cnt * 4 + threadIdx.x; z < POST * 4; z += 128)
        out[OUT_ROIS + (size_t)nb * POST * 4 + z] = 0.0f;
}

// ---------------- launcher ----------------
extern "C" void kernel_launch(void* const* d_in, const int* in_sizes, int n_in,
                              void* d_out, int out_size) {
    const float* x  = (const float*)d_in[0];
    const float* w1 = (const float*)d_in[1];
    const float* b1 = (const float*)d_in[2];
    const float* sw = (const float*)d_in[3];
    const float* sb = (const float*)d_in[4];
    const float* lw = (const float*)d_in[5];
    const float* lb = (const float*)d_in[6];
    const void*  ph = d_in[7];
    const void*  pw = d_in[8];
    float* out = (float*)d_out;

    cudaFuncSetAttribute(k_convh, cudaFuncAttributeMaxDynamicSharedMemorySize,
                         2 * BUFSZ);

    k_split_w<<<(COUT * KTOT + 255) / 256, 256>>>(w1);
    k_split_x<<<dim3(119, 16, NB), dim3(32, 32)>>>(x);
    k_anchor<<<(NANCH + 255) / 256, 256>>>(out);
    k_convh<<<dim3(30, 4, NB), 512, 2 * BUFSZ>>>(b1);
    k_heads<<<dim3(15, NB), 128>>>(sw, sb, lw, lb, out);
    k_decode<<<dim3(SORTN / 256, NB), 256>>>(out, ph, pw);
    k_sort_local<<<dim3(16, NB), 512>>>();
    for (int k = 8192; k <= 65536; k <<= 1) {
        for (int j = k >> 1; j >= 4096; j >>= 1)
            k_sort_global<<<dim3(128, NB), 256>>>(k, j);
        k_sort_tail<<<dim3(16, NB), 512>>>(k);
    }
    k_gather<<<dim3((PRE + 255) / 256, NB), 256>>>();
    k_mask<<<dim3(NW, NW, NB), 64>>>();
    k_scan<<<NB, 128>>>(out);
}